// round 7
// baseline (speedup 1.0000x reference)
#include <cuda_runtime.h>
#include <cuda_bf16.h>
#include <cooperative_groups.h>

namespace cg = cooperative_groups;

#define RB      4
#define BINS    64      // RB^3
#define BATCH   64
#define CLS     40
#define THREADS 1024
#define NWARP   (THREADS / 32)

__global__ void __cluster_dims__(2, 1, 1) __launch_bounds__(THREADS, 1)
k_fused(const float* __restrict__ x, const float* __restrict__ W,
        const float* __restrict__ bias, float* __restrict__ out,
        int N, int nTiles, int tailStart, float invN)
{
    __shared__ float sWt[BINS * CLS];   // W transposed: sWt[k*CLS + c]
    __shared__ int   sh[NWARP * BINS];  // per-warp histograms (STS at end)
    __shared__ float sred[NWARP][6];
    __shared__ float sblk[6];           // this CTA's mn0..2, mx0..2
    __shared__ float sfin[6];           // cluster-combined
    __shared__ int   hfin[BINS];
    __shared__ float sc[BINS];

    cg::cluster_group cluster = cg::this_cluster();
    const int rank = cluster.block_rank();   // 0 or 1
    const int bat  = blockIdx.y;
    const int tid  = threadIdx.x;
    const int lane = tid & 31, warp = tid >> 5;
    const int gwarp = rank * NWARP + warp;   // 0..63 across cluster
    const int ctid  = rank * THREADS + tid;  // 0..2047 across cluster
    const int lr    = lane % 3;

    const float*  xb = x + (size_t)bat * 3u * (size_t)N;
    const float4* p4 = (const float4*)xb;

    if (rank == 0) {
        for (int i = tid; i < CLS * BINS; i += THREADS) {
            int c = i >> 6, k = i & 63;
            sWt[k * CLS + c] = W[i];
        }
    }

    // ================= Pass 1: min/max, coalesced =================
    const float FMAX =  3.402823466e38f;
    float mnA0 = FMAX, mnA1 = FMAX, mnA2 = FMAX;
    float mnB0 = FMAX, mnB1 = FMAX, mnB2 = FMAX;
    float mnC0 = FMAX, mnC1 = FMAX, mnC2 = FMAX;
    float mxA0 = -FMAX, mxA1 = -FMAX, mxA2 = -FMAX;
    float mxB0 = -FMAX, mxB1 = -FMAX, mxB2 = -FMAX;
    float mxC0 = -FMAX, mxC1 = -FMAX, mxC2 = -FMAX;

    for (int t = gwarp; t < nTiles; t += 2 * NWARP) {
        int b96 = t * 96;
        float4 A = p4[b96 + lane];
        float4 B = p4[b96 + 32 + lane];
        float4 C = p4[b96 + 64 + lane];
        float tn, tx;
        tn = fminf(A.x, A.w); tx = fmaxf(A.x, A.w);
        mnA0 = fminf(mnA0, tn);  mxA0 = fmaxf(mxA0, tx);
        mnA1 = fminf(mnA1, A.y); mxA1 = fmaxf(mxA1, A.y);
        mnA2 = fminf(mnA2, A.z); mxA2 = fmaxf(mxA2, A.z);
        tn = fminf(B.x, B.w); tx = fmaxf(B.x, B.w);
        mnB0 = fminf(mnB0, tn);  mxB0 = fmaxf(mxB0, tx);
        mnB1 = fminf(mnB1, B.y); mxB1 = fmaxf(mxB1, B.y);
        mnB2 = fminf(mnB2, B.z); mxB2 = fmaxf(mxB2, B.z);
        tn = fminf(C.x, C.w); tx = fmaxf(C.x, C.w);
        mnC0 = fminf(mnC0, tn);  mxC0 = fmaxf(mxC0, tx);
        mnC1 = fminf(mnC1, C.y); mxC1 = fmaxf(mxC1, C.y);
        mnC2 = fminf(mnC2, C.z); mxC2 = fmaxf(mxC2, C.z);
    }

    // Slot phases -> absolute components: comp_c = G_{(c - lr) mod 3}
    float Gn0 = fminf(mnA0, fminf(mnB1, mnC2));
    float Gn1 = fminf(mnA1, fminf(mnB2, mnC0));
    float Gn2 = fminf(mnA2, fminf(mnB0, mnC1));
    float Gx0 = fmaxf(mxA0, fmaxf(mxB1, mxC2));
    float Gx1 = fmaxf(mxA1, fmaxf(mxB2, mxC0));
    float Gx2 = fmaxf(mxA2, fmaxf(mxB0, mxC1));
    float mn0 = (lr == 0) ? Gn0 : (lr == 1) ? Gn2 : Gn1;
    float mn1 = (lr == 0) ? Gn1 : (lr == 1) ? Gn0 : Gn2;
    float mn2 = (lr == 0) ? Gn2 : (lr == 1) ? Gn1 : Gn0;
    float mx0 = (lr == 0) ? Gx0 : (lr == 1) ? Gx2 : Gx1;
    float mx1 = (lr == 0) ? Gx1 : (lr == 1) ? Gx0 : Gx2;
    float mx2 = (lr == 0) ? Gx2 : (lr == 1) ? Gx1 : Gx0;

    for (int j = tailStart + ctid; j < N; j += 2 * THREADS) {
        float vx = xb[3 * j + 0], vy = xb[3 * j + 1], vz = xb[3 * j + 2];
        mn0 = fminf(mn0, vx); mx0 = fmaxf(mx0, vx);
        mn1 = fminf(mn1, vy); mx1 = fmaxf(mx1, vy);
        mn2 = fminf(mn2, vz); mx2 = fmaxf(mx2, vz);
    }

    #pragma unroll
    for (int off = 16; off > 0; off >>= 1) {
        mn0 = fminf(mn0, __shfl_xor_sync(0xffffffffu, mn0, off));
        mn1 = fminf(mn1, __shfl_xor_sync(0xffffffffu, mn1, off));
        mn2 = fminf(mn2, __shfl_xor_sync(0xffffffffu, mn2, off));
        mx0 = fmaxf(mx0, __shfl_xor_sync(0xffffffffu, mx0, off));
        mx1 = fmaxf(mx1, __shfl_xor_sync(0xffffffffu, mx1, off));
        mx2 = fmaxf(mx2, __shfl_xor_sync(0xffffffffu, mx2, off));
    }
    if (lane == 0) {
        sred[warp][0] = mn0; sred[warp][1] = mn1; sred[warp][2] = mn2;
        sred[warp][3] = mx0; sred[warp][4] = mx1; sred[warp][5] = mx2;
    }
    __syncthreads();
    if (warp == 0) {   // NWARP == 32
        float v0 = sred[lane][0], v1 = sred[lane][1], v2 = sred[lane][2];
        float v3 = sred[lane][3], v4 = sred[lane][4], v5 = sred[lane][5];
        #pragma unroll
        for (int off = 16; off > 0; off >>= 1) {
            v0 = fminf(v0, __shfl_xor_sync(0xffffffffu, v0, off));
            v1 = fminf(v1, __shfl_xor_sync(0xffffffffu, v1, off));
            v2 = fminf(v2, __shfl_xor_sync(0xffffffffu, v2, off));
            v3 = fmaxf(v3, __shfl_xor_sync(0xffffffffu, v3, off));
            v4 = fmaxf(v4, __shfl_xor_sync(0xffffffffu, v4, off));
            v5 = fmaxf(v5, __shfl_xor_sync(0xffffffffu, v5, off));
        }
        if (lane == 0) {
            sblk[0] = v0; sblk[1] = v1; sblk[2] = v2;
            sblk[3] = v3; sblk[4] = v4; sblk[5] = v5;
        }
    }

    // ---- Cluster exchange of min/max ----
    cluster.sync();
    if (tid < 3) {
        const float* peer = cluster.map_shared_rank(sblk, rank ^ 1);
        sfin[tid]     = fminf(sblk[tid],     peer[tid]);
        sfin[tid + 3] = fmaxf(sblk[tid + 3], peer[tid + 3]);
    }
    __syncthreads();
    const float fm0 = sfin[0], fm1 = sfin[1], fm2 = sfin[2];
    // Shrunken scale + bias: guarantees idx in [0, RB-1] with NO clamps.
    const float s0 = 3.99999f / (sfin[3] - fm0);
    const float s1 = 3.99999f / (sfin[4] - fm1);
    const float s2 = 3.99999f / (sfin[5] - fm2);
    const float t0 = 1e-6f - fm0 * s0;
    const float t1 = 1e-6f - fm1 * s1;
    const float t2 = 1e-6f - fm2 * s2;

    // ================= Pass 2: ballot histogram (atomic-free) =============
    // Lane owns bins `lane` and `lane+32`. Bit layout: bin = i0*16+i1*4+i2
    //   bit5 = i0>>1, bit4 = i0&1, bit3 = i1>>1, bit2 = i1&1,
    //   bit1 = i2>>1, bit0 = i2&1
    const unsigned eA0 = (lane & 16) ? 0u : 0xFFFFFFFFu;  // bit4
    const unsigned eB1 = (lane &  8) ? 0u : 0xFFFFFFFFu;  // bit3
    const unsigned eB0 = (lane &  4) ? 0u : 0xFFFFFFFFu;  // bit2
    const unsigned eC1 = (lane &  2) ? 0u : 0xFFFFFFFFu;  // bit1
    const unsigned eC0 = (lane &  1) ? 0u : 0xFFFFFFFFu;  // bit0
    int cnt1 = 0, cnt2 = 0;

    #define BALLOT_BIN(px, py, pz)                                           \
        do {                                                                 \
            int i0_ = __float2int_rd(fmaf((px), s0, t0));                    \
            int i1_ = __float2int_rd(fmaf((py), s1, t1));                    \
            int i2_ = __float2int_rd(fmaf((pz), s2, t2));                    \
            unsigned A0_ = __ballot_sync(0xffffffffu, i0_ & 1);              \
            unsigned A1_ = __ballot_sync(0xffffffffu, i0_ & 2);              \
            unsigned B0_ = __ballot_sync(0xffffffffu, i1_ & 1);              \
            unsigned B1_ = __ballot_sync(0xffffffffu, i1_ & 2);              \
            unsigned C0_ = __ballot_sync(0xffffffffu, i2_ & 1);              \
            unsigned C1_ = __ballot_sync(0xffffffffu, i2_ & 2);              \
            unsigned m_ = (A0_ ^ eA0) & (B1_ ^ eB1) & (B0_ ^ eB0)            \
                        & (C1_ ^ eC1) & (C0_ ^ eC0);                         \
            cnt1 += __popc(m_ & ~A1_);                                       \
            cnt2 += __popc(m_ &  A1_);                                       \
        } while (0)

    // Per-lane point assembly (same as R5): row m offset o_m = (m - lr) mod 3
    const int  o0 = (3 - lr) % 3, o1 = (4 - lr) % 3, o2 = (5 - lr) % 3;
    const bool e00 = (o0 == 0), e01 = (o0 == 1);
    const bool e10 = (o1 == 0), e11 = (o1 == 1);
    const bool e20 = (o2 == 0), e21 = (o2 == 1);
    const bool r0 = (lr == 0), r1 = (lr == 1);

    for (int t = gwarp; t < nTiles; t += 2 * NWARP) {
        int b96 = t * 96;
        float4 v0 = p4[b96 + lane];
        float4 v1 = p4[b96 + 32 + lane];
        float4 v2 = p4[b96 + 64 + lane];

        float nx0 = __shfl_down_sync(0xffffffffu, v0.x, 1);
        float ny0 = __shfl_down_sync(0xffffffffu, v0.y, 1);
        float nx1 = __shfl_down_sync(0xffffffffu, v1.x, 1);
        float ny1 = __shfl_down_sync(0xffffffffu, v1.y, 1);
        float nx2 = __shfl_down_sync(0xffffffffu, v2.x, 1);
        float ny2 = __shfl_down_sync(0xffffffffu, v2.y, 1);
        float b1x = __shfl_sync(0xffffffffu, v1.x, 0);
        float b1y = __shfl_sync(0xffffffffu, v1.y, 0);
        float b2x = __shfl_sync(0xffffffffu, v2.x, 0);
        float b2y = __shfl_sync(0xffffffffu, v2.y, 0);
        if (lane == 31) { nx0 = b1x; ny0 = b1y; nx1 = b2x; ny1 = b2y; }

        {
            float ax = e00 ? v0.x : e01 ? v0.y : v0.z;
            float ay = e00 ? v0.y : e01 ? v0.z : v0.w;
            float az = e00 ? v0.z : e01 ? v0.w : nx0;
            BALLOT_BIN(ax, ay, az);
        }
        {
            float ax = e10 ? v1.x : e11 ? v1.y : v1.z;
            float ay = e10 ? v1.y : e11 ? v1.z : v1.w;
            float az = e10 ? v1.z : e11 ? v1.w : nx1;
            BALLOT_BIN(ax, ay, az);
        }
        {
            float ax = e20 ? v2.x : e21 ? v2.y : v2.z;
            float ay = e20 ? v2.y : e21 ? v2.z : v2.w;
            float az = e20 ? v2.z : e21 ? v2.w : nx2;
            BALLOT_BIN(ax, ay, az);
        }
        {
            float bx = r0 ? v0.w : r1 ? v1.w : v2.w;
            float by = r0 ? nx0  : r1 ? nx1  : nx2;
            float bz = r0 ? ny0  : r1 ? ny1  : ny2;
            BALLOT_BIN(bx, by, bz);
        }
    }

    // Per-warp register counters -> smem (plain stores, no atomics)
    sh[(warp << 6) + lane]      = cnt1;
    sh[(warp << 6) + 32 + lane] = cnt2;
    __syncthreads();

    // Tail points (32 for N=100000): atomics into warp-0's row
    for (int j = tailStart + ctid; j < N; j += 2 * THREADS) {
        int i0_ = __float2int_rd(fmaf(xb[3 * j + 0], s0, t0));
        int i1_ = __float2int_rd(fmaf(xb[3 * j + 1], s1, t1));
        int i2_ = __float2int_rd(fmaf(xb[3 * j + 2], s2, t2));
        atomicAdd(&sh[i0_ * 16 + i1_ * 4 + i2_], 1);
    }
    __syncthreads();

    if (tid < BINS) {
        int s = 0;
        #pragma unroll
        for (int w = 0; w < NWARP; w++) s += sh[(w << 6) + tid];
        hfin[tid] = s;
    }

    // ---- Cluster hist merge + epilogue (rank 0) ----
    cluster.sync();
    if (rank == 0 && tid < BINS) {
        const int* peer = cluster.map_shared_rank(hfin, 1);
        sc[tid] = (float)(hfin[tid] + peer[tid]) * invN;
    }
    cluster.sync();   // rank 1 must not exit before rank 0 read its smem

    if (rank == 0) {
        __syncthreads();
        if (tid < CLS) {
            float acc = bias[tid];
            #pragma unroll
            for (int k = 0; k < BINS; k++)
                acc = fmaf(sc[k], sWt[k * CLS + tid], acc);
            out[bat * CLS + tid] = acc;
        }
    }
}

extern "C" void kernel_launch(void* const* d_in, const int* in_sizes, int n_in,
                              void* d_out, int out_size) {
    const float* x = (const float*)d_in[0];
    const float* W = (const float*)d_in[1];
    const float* b = (const float*)d_in[2];
    float* out = (float*)d_out;

    int N = in_sizes[0] / (BATCH * 3);   // 100000
    int nf4    = ((3 * N) % 4 == 0) ? (3 * N) / 4 : 0;
    int nTiles = nf4 / 96;
    int tailStart = nTiles * 128;

    dim3 grid(2, BATCH);
    k_fused<<<grid, THREADS>>>(x, W, b, out, N, nTiles, tailStart,
                               1.0f / (float)N);
}

// round 9
// speedup vs baseline: 1.3380x; 1.3380x over previous
#include <cuda_runtime.h>
#include <cuda_bf16.h>
#include <cooperative_groups.h>

namespace cg = cooperative_groups;

#define RB      4
#define BINS    64      // RB^3
#define BATCH   64
#define CLS     40
#define THREADS 1024
#define NWARP   (THREADS / 32)

__global__ void __cluster_dims__(2, 1, 1) __launch_bounds__(THREADS, 1)
k_fused(const float* __restrict__ x, const float* __restrict__ W,
        const float* __restrict__ bias, float* __restrict__ out,
        int N, int nTiles, int tailStart, float invN)
{
    __shared__ float sWt[BINS * CLS];   // W transposed: sWt[k*CLS + c]
    __shared__ int   sh[NWARP * BINS];  // per-warp sub-histograms
    __shared__ float sred[NWARP][6];
    __shared__ float sblk[6];           // this CTA's mn0..2, mx0..2
    __shared__ float sfin[6];           // cluster-combined
    __shared__ int   hfin[BINS];
    __shared__ float sc[BINS];

    cg::cluster_group cluster = cg::this_cluster();
    const int rank = cluster.block_rank();   // 0 or 1
    const int bat  = blockIdx.y;
    const int tid  = threadIdx.x;
    const int lane = tid & 31, warp = tid >> 5;
    const int gwarp = rank * NWARP + warp;   // 0..63 across cluster
    const int ctid  = rank * THREADS + tid;  // 0..2047 across cluster
    const int lr    = lane % 3;

    const float*  xb = x + (size_t)bat * 3u * (size_t)N;
    const float4* p4 = (const float4*)xb;

    if (rank == 0) {
        for (int i = tid; i < CLS * BINS; i += THREADS) {
            int c = i >> 6, k = i & 63;
            sWt[k * CLS + c] = W[i];
        }
    }
    for (int i = tid; i < NWARP * BINS; i += THREADS) sh[i] = 0;

    // ================= Pass 1: min/max, coalesced + prefetch ==============
    const float FMAX =  3.402823466e38f;
    float mnA0 = FMAX, mnA1 = FMAX, mnA2 = FMAX;
    float mnB0 = FMAX, mnB1 = FMAX, mnB2 = FMAX;
    float mnC0 = FMAX, mnC1 = FMAX, mnC2 = FMAX;
    float mxA0 = -FMAX, mxA1 = -FMAX, mxA2 = -FMAX;
    float mxB0 = -FMAX, mxB1 = -FMAX, mxB2 = -FMAX;
    float mxC0 = -FMAX, mxC1 = -FMAX, mxC2 = -FMAX;

    if (gwarp < nTiles) {
        int t = gwarp;
        float4 A = p4[t * 96 + lane];
        float4 B = p4[t * 96 + 32 + lane];
        float4 C = p4[t * 96 + 64 + lane];
        for (;;) {
            int  tn   = t + 2 * NWARP;
            bool more = tn < nTiles;
            int  tl   = more ? tn : t;       // clamped: safe, L1-hit if dead
            float4 An = p4[tl * 96 + lane];
            float4 Bn = p4[tl * 96 + 32 + lane];
            float4 Cn = p4[tl * 96 + 64 + lane];

            float tn_, tx_;
            tn_ = fminf(A.x, A.w); tx_ = fmaxf(A.x, A.w);
            mnA0 = fminf(mnA0, tn_); mxA0 = fmaxf(mxA0, tx_);
            mnA1 = fminf(mnA1, A.y); mxA1 = fmaxf(mxA1, A.y);
            mnA2 = fminf(mnA2, A.z); mxA2 = fmaxf(mxA2, A.z);
            tn_ = fminf(B.x, B.w); tx_ = fmaxf(B.x, B.w);
            mnB0 = fminf(mnB0, tn_); mxB0 = fmaxf(mxB0, tx_);
            mnB1 = fminf(mnB1, B.y); mxB1 = fmaxf(mxB1, B.y);
            mnB2 = fminf(mnB2, B.z); mxB2 = fmaxf(mxB2, B.z);
            tn_ = fminf(C.x, C.w); tx_ = fmaxf(C.x, C.w);
            mnC0 = fminf(mnC0, tn_); mxC0 = fmaxf(mxC0, tx_);
            mnC1 = fminf(mnC1, C.y); mxC1 = fmaxf(mxC1, C.y);
            mnC2 = fminf(mnC2, C.z); mxC2 = fmaxf(mxC2, C.z);

            if (!more) break;
            t = tn; A = An; B = Bn; C = Cn;
        }
    }

    // Slot phases -> absolute components: comp_c = G_{(c - lr) mod 3}
    float Gn0 = fminf(mnA0, fminf(mnB1, mnC2));
    float Gn1 = fminf(mnA1, fminf(mnB2, mnC0));
    float Gn2 = fminf(mnA2, fminf(mnB0, mnC1));
    float Gx0 = fmaxf(mxA0, fmaxf(mxB1, mxC2));
    float Gx1 = fmaxf(mxA1, fmaxf(mxB2, mxC0));
    float Gx2 = fmaxf(mxA2, fmaxf(mxB0, mxC1));
    float mn0 = (lr == 0) ? Gn0 : (lr == 1) ? Gn2 : Gn1;
    float mn1 = (lr == 0) ? Gn1 : (lr == 1) ? Gn0 : Gn2;
    float mn2 = (lr == 0) ? Gn2 : (lr == 1) ? Gn1 : Gn0;
    float mx0 = (lr == 0) ? Gx0 : (lr == 1) ? Gx2 : Gx1;
    float mx1 = (lr == 0) ? Gx1 : (lr == 1) ? Gx0 : Gx2;
    float mx2 = (lr == 0) ? Gx2 : (lr == 1) ? Gx1 : Gx0;

    for (int j = tailStart + ctid; j < N; j += 2 * THREADS) {
        float vx = xb[3 * j + 0], vy = xb[3 * j + 1], vz = xb[3 * j + 2];
        mn0 = fminf(mn0, vx); mx0 = fmaxf(mx0, vx);
        mn1 = fminf(mn1, vy); mx1 = fmaxf(mx1, vy);
        mn2 = fminf(mn2, vz); mx2 = fmaxf(mx2, vz);
    }

    #pragma unroll
    for (int off = 16; off > 0; off >>= 1) {
        mn0 = fminf(mn0, __shfl_xor_sync(0xffffffffu, mn0, off));
        mn1 = fminf(mn1, __shfl_xor_sync(0xffffffffu, mn1, off));
        mn2 = fminf(mn2, __shfl_xor_sync(0xffffffffu, mn2, off));
        mx0 = fmaxf(mx0, __shfl_xor_sync(0xffffffffu, mx0, off));
        mx1 = fmaxf(mx1, __shfl_xor_sync(0xffffffffu, mx1, off));
        mx2 = fmaxf(mx2, __shfl_xor_sync(0xffffffffu, mx2, off));
    }
    if (lane == 0) {
        sred[warp][0] = mn0; sred[warp][1] = mn1; sred[warp][2] = mn2;
        sred[warp][3] = mx0; sred[warp][4] = mx1; sred[warp][5] = mx2;
    }
    __syncthreads();
    if (warp == 0) {   // NWARP == 32
        float v0 = sred[lane][0], v1 = sred[lane][1], v2 = sred[lane][2];
        float v3 = sred[lane][3], v4 = sred[lane][4], v5 = sred[lane][5];
        #pragma unroll
        for (int off = 16; off > 0; off >>= 1) {
            v0 = fminf(v0, __shfl_xor_sync(0xffffffffu, v0, off));
            v1 = fminf(v1, __shfl_xor_sync(0xffffffffu, v1, off));
            v2 = fminf(v2, __shfl_xor_sync(0xffffffffu, v2, off));
            v3 = fmaxf(v3, __shfl_xor_sync(0xffffffffu, v3, off));
            v4 = fmaxf(v4, __shfl_xor_sync(0xffffffffu, v4, off));
            v5 = fmaxf(v5, __shfl_xor_sync(0xffffffffu, v5, off));
        }
        if (lane == 0) {
            sblk[0] = v0; sblk[1] = v1; sblk[2] = v2;
            sblk[3] = v3; sblk[4] = v4; sblk[5] = v5;
        }
    }

    // ---- Cluster exchange of min/max ----
    cluster.sync();
    if (tid < 3) {
        const float* peer = cluster.map_shared_rank(sblk, rank ^ 1);
        sfin[tid]     = fminf(sblk[tid],     peer[tid]);
        sfin[tid + 3] = fmaxf(sblk[tid + 3], peer[tid + 3]);
    }
    __syncthreads();
    const float fm0 = sfin[0], fm1 = sfin[1], fm2 = sfin[2];
    // Shrunken scale + bias: guarantees idx in [0, RB-1] with NO clamps.
    const float s0 = 3.99999f / (sfin[3] - fm0);
    const float s1 = 3.99999f / (sfin[4] - fm1);
    const float s2 = 3.99999f / (sfin[5] - fm2);
    const float t0 = 1e-6f - fm0 * s0;
    const float t1 = 1e-6f - fm1 * s1;
    const float t2 = 1e-6f - fm2 * s2;

    // ============== Pass 2: histogram, coalesced + prefetch ===============
    int* myh = &sh[warp << 6];

    #define BIN3(px, py, pz)                                                 \
        do {                                                                 \
            int i0_ = __float2int_rd(fmaf((px), s0, t0));                    \
            int i1_ = __float2int_rd(fmaf((py), s1, t1));                    \
            int i2_ = __float2int_rd(fmaf((pz), s2, t2));                    \
            atomicAdd(&myh[i0_ * 16 + i1_ * 4 + i2_], 1);                    \
        } while (0)

    // Row m has start-offset sigma=m; per-lane o_m = (m - lr) mod 3.
    const int  o0 = (3 - lr) % 3, o1 = (4 - lr) % 3, o2 = (5 - lr) % 3;
    const bool e00 = (o0 == 0), e01 = (o0 == 1);
    const bool e10 = (o1 == 0), e11 = (o1 == 1);
    const bool e20 = (o2 == 0), e21 = (o2 == 1);
    const bool r0 = (lr == 0), r1 = (lr == 1);

    if (gwarp < nTiles) {
        int t = gwarp;
        float4 v0 = p4[t * 96 + lane];
        float4 v1 = p4[t * 96 + 32 + lane];
        float4 v2 = p4[t * 96 + 64 + lane];
        for (;;) {
            int  tn   = t + 2 * NWARP;
            bool more = tn < nTiles;
            int  tl   = more ? tn : t;
            float4 u0 = p4[tl * 96 + lane];
            float4 u1 = p4[tl * 96 + 32 + lane];
            float4 u2 = p4[tl * 96 + 64 + lane];

            float nx0 = __shfl_down_sync(0xffffffffu, v0.x, 1);
            float ny0 = __shfl_down_sync(0xffffffffu, v0.y, 1);
            float nx1 = __shfl_down_sync(0xffffffffu, v1.x, 1);
            float ny1 = __shfl_down_sync(0xffffffffu, v1.y, 1);
            float nx2 = __shfl_down_sync(0xffffffffu, v2.x, 1);
            float ny2 = __shfl_down_sync(0xffffffffu, v2.y, 1);
            // lane 31: next floats come from lane 0 of the NEXT row
            float b1x = __shfl_sync(0xffffffffu, v1.x, 0);
            float b1y = __shfl_sync(0xffffffffu, v1.y, 0);
            float b2x = __shfl_sync(0xffffffffu, v2.x, 0);
            float b2y = __shfl_sync(0xffffffffu, v2.y, 0);
            if (lane == 31) { nx0 = b1x; ny0 = b1y; nx1 = b2x; ny1 = b2y; }

            // Row A-points: window f0..f4 = (v.x,v.y,v.z,v.w,nx)
            {
                float ax = e00 ? v0.x : e01 ? v0.y : v0.z;
                float ay = e00 ? v0.y : e01 ? v0.z : v0.w;
                float az = e00 ? v0.z : e01 ? v0.w : nx0;
                BIN3(ax, ay, az);
            }
            {
                float ax = e10 ? v1.x : e11 ? v1.y : v1.z;
                float ay = e10 ? v1.y : e11 ? v1.z : v1.w;
                float az = e10 ? v1.z : e11 ? v1.w : nx1;
                BIN3(ax, ay, az);
            }
            {
                float ax = e20 ? v2.x : e21 ? v2.y : v2.z;
                float ay = e20 ? v2.y : e21 ? v2.z : v2.w;
                float az = e20 ? v2.z : e21 ? v2.w : nx2;
                BIN3(ax, ay, az);
            }
            // B-point: the one row with o==0 (row index == lr): (f3,f4,f5)
            {
                float bx = r0 ? v0.w : r1 ? v1.w : v2.w;
                float by = r0 ? nx0  : r1 ? nx1  : nx2;
                float bz = r0 ? ny0  : r1 ? ny1  : ny2;
                BIN3(bx, by, bz);
            }

            if (!more) break;
            t = tn; v0 = u0; v1 = u1; v2 = u2;
        }
    }
    // Tail points
    for (int j = tailStart + ctid; j < N; j += 2 * THREADS) {
        BIN3(xb[3 * j + 0], xb[3 * j + 1], xb[3 * j + 2]);
    }
    __syncthreads();

    if (tid < BINS) {
        int s = 0;
        #pragma unroll
        for (int w = 0; w < NWARP; w++) s += sh[(w << 6) + tid];
        hfin[tid] = s;
    }

    // ---- Cluster hist merge + epilogue (rank 0) ----
    cluster.sync();
    if (rank == 0 && tid < BINS) {
        const int* peer = cluster.map_shared_rank(hfin, 1);
        sc[tid] = (float)(hfin[tid] + peer[tid]) * invN;
    }
    cluster.sync();   // rank 1 must not exit before rank 0 read its smem

    if (rank == 0) {
        __syncthreads();
        if (tid < CLS) {
            float acc = bias[tid];
            #pragma unroll
            for (int k = 0; k < BINS; k++)
                acc = fmaf(sc[k], sWt[k * CLS + tid], acc);
            out[bat * CLS + tid] = acc;
        }
    }
}

extern "C" void kernel_launch(void* const* d_in, const int* in_sizes, int n_in,
                              void* d_out, int out_size) {
    const float* x = (const float*)d_in[0];
    const float* W = (const float*)d_in[1];
    const float* b = (const float*)d_in[2];
    float* out = (float*)d_out;

    int N = in_sizes[0] / (BATCH * 3);   // 100000
    int nf4    = ((3 * N) % 4 == 0) ? (3 * N) / 4 : 0;
    int nTiles = nf4 / 96;
    int tailStart = nTiles * 128;

    dim3 grid(2, BATCH);
    k_fused<<<grid, THREADS>>>(x, W, b, out, N, nTiles, tailStart,
                               1.0f / (float)N);
}

// round 10
// speedup vs baseline: 1.4488x; 1.0828x over previous
#include <cuda_runtime.h>
#include <cuda_bf16.h>
#include <cooperative_groups.h>

namespace cg = cooperative_groups;

#define RB      4
#define BINS    64      // RB^3
#define BATCH   64
#define CLS     40
#define THREADS 1024
#define NWARP   (THREADS / 32)

__global__ void __cluster_dims__(2, 1, 1) __launch_bounds__(THREADS, 1)
k_fused(const float* __restrict__ x, const float* __restrict__ W,
        const float* __restrict__ bias, float* __restrict__ out,
        int N, int nTiles, int tailStart, float invN)
{
    __shared__ float sWt[BINS * CLS];   // W transposed: sWt[k*CLS + c]
    __shared__ int   sh[NWARP * BINS];  // per-warp sub-histograms
    __shared__ float sred[NWARP][6];
    __shared__ float sblk[6];           // this CTA's mn0..2, mx0..2
    __shared__ float sfin[6];           // cluster-combined
    __shared__ int   hfin[BINS];
    __shared__ float sc[BINS];

    cg::cluster_group cluster = cg::this_cluster();
    const int rank = cluster.block_rank();   // 0 or 1
    const int bat  = blockIdx.y;
    const int tid  = threadIdx.x;
    const int lane = tid & 31, warp = tid >> 5;
    const int gwarp = rank * NWARP + warp;   // 0..63 across cluster
    const int ctid  = rank * THREADS + tid;  // 0..2047 across cluster
    const int lr    = lane % 3;

    const float*  xb = x + (size_t)bat * 3u * (size_t)N;
    const float4* p4 = (const float4*)xb;

    if (rank == 0) {
        for (int i = tid; i < CLS * BINS; i += THREADS) {
            int c = i >> 6, k = i & 63;
            sWt[k * CLS + c] = W[i];
        }
    }
    for (int i = tid; i < NWARP * BINS; i += THREADS) sh[i] = 0;

    // ================= Pass 1: min/max, coalesced =================
    const float FMAX =  3.402823466e38f;
    float mnA0 = FMAX, mnA1 = FMAX, mnA2 = FMAX;
    float mnB0 = FMAX, mnB1 = FMAX, mnB2 = FMAX;
    float mnC0 = FMAX, mnC1 = FMAX, mnC2 = FMAX;
    float mxA0 = -FMAX, mxA1 = -FMAX, mxA2 = -FMAX;
    float mxB0 = -FMAX, mxB1 = -FMAX, mxB2 = -FMAX;
    float mxC0 = -FMAX, mxC1 = -FMAX, mxC2 = -FMAX;

    for (int t = gwarp; t < nTiles; t += 2 * NWARP) {
        int b96 = t * 96;
        float4 A = p4[b96 + lane];
        float4 B = p4[b96 + 32 + lane];
        float4 C = p4[b96 + 64 + lane];
        float tn, tx;
        tn = fminf(A.x, A.w); tx = fmaxf(A.x, A.w);
        mnA0 = fminf(mnA0, tn);  mxA0 = fmaxf(mxA0, tx);
        mnA1 = fminf(mnA1, A.y); mxA1 = fmaxf(mxA1, A.y);
        mnA2 = fminf(mnA2, A.z); mxA2 = fmaxf(mxA2, A.z);
        tn = fminf(B.x, B.w); tx = fmaxf(B.x, B.w);
        mnB0 = fminf(mnB0, tn);  mxB0 = fmaxf(mxB0, tx);
        mnB1 = fminf(mnB1, B.y); mxB1 = fmaxf(mxB1, B.y);
        mnB2 = fminf(mnB2, B.z); mxB2 = fmaxf(mxB2, B.z);
        tn = fminf(C.x, C.w); tx = fmaxf(C.x, C.w);
        mnC0 = fminf(mnC0, tn);  mxC0 = fmaxf(mxC0, tx);
        mnC1 = fminf(mnC1, C.y); mxC1 = fmaxf(mxC1, C.y);
        mnC2 = fminf(mnC2, C.z); mxC2 = fmaxf(mxC2, C.z);
    }

    // Slot phases -> absolute components: comp_c = G_{(c - lr) mod 3}
    float Gn0 = fminf(mnA0, fminf(mnB1, mnC2));
    float Gn1 = fminf(mnA1, fminf(mnB2, mnC0));
    float Gn2 = fminf(mnA2, fminf(mnB0, mnC1));
    float Gx0 = fmaxf(mxA0, fmaxf(mxB1, mxC2));
    float Gx1 = fmaxf(mxA1, fmaxf(mxB2, mxC0));
    float Gx2 = fmaxf(mxA2, fmaxf(mxB0, mxC1));
    float mn0 = (lr == 0) ? Gn0 : (lr == 1) ? Gn2 : Gn1;
    float mn1 = (lr == 0) ? Gn1 : (lr == 1) ? Gn0 : Gn2;
    float mn2 = (lr == 0) ? Gn2 : (lr == 1) ? Gn1 : Gn0;
    float mx0 = (lr == 0) ? Gx0 : (lr == 1) ? Gx2 : Gx1;
    float mx1 = (lr == 0) ? Gx1 : (lr == 1) ? Gx0 : Gx2;
    float mx2 = (lr == 0) ? Gx2 : (lr == 1) ? Gx1 : Gx0;

    for (int j = tailStart + ctid; j < N; j += 2 * THREADS) {
        float vx = xb[3 * j + 0], vy = xb[3 * j + 1], vz = xb[3 * j + 2];
        mn0 = fminf(mn0, vx); mx0 = fmaxf(mx0, vx);
        mn1 = fminf(mn1, vy); mx1 = fmaxf(mx1, vy);
        mn2 = fminf(mn2, vz); mx2 = fmaxf(mx2, vz);
    }

    #pragma unroll
    for (int off = 16; off > 0; off >>= 1) {
        mn0 = fminf(mn0, __shfl_xor_sync(0xffffffffu, mn0, off));
        mn1 = fminf(mn1, __shfl_xor_sync(0xffffffffu, mn1, off));
        mn2 = fminf(mn2, __shfl_xor_sync(0xffffffffu, mn2, off));
        mx0 = fmaxf(mx0, __shfl_xor_sync(0xffffffffu, mx0, off));
        mx1 = fmaxf(mx1, __shfl_xor_sync(0xffffffffu, mx1, off));
        mx2 = fmaxf(mx2, __shfl_xor_sync(0xffffffffu, mx2, off));
    }
    if (lane == 0) {
        sred[warp][0] = mn0; sred[warp][1] = mn1; sred[warp][2] = mn2;
        sred[warp][3] = mx0; sred[warp][4] = mx1; sred[warp][5] = mx2;
    }
    __syncthreads();
    if (warp == 0) {   // NWARP == 32
        float v0 = sred[lane][0], v1 = sred[lane][1], v2 = sred[lane][2];
        float v3 = sred[lane][3], v4 = sred[lane][4], v5 = sred[lane][5];
        #pragma unroll
        for (int off = 16; off > 0; off >>= 1) {
            v0 = fminf(v0, __shfl_xor_sync(0xffffffffu, v0, off));
            v1 = fminf(v1, __shfl_xor_sync(0xffffffffu, v1, off));
            v2 = fminf(v2, __shfl_xor_sync(0xffffffffu, v2, off));
            v3 = fmaxf(v3, __shfl_xor_sync(0xffffffffu, v3, off));
            v4 = fmaxf(v4, __shfl_xor_sync(0xffffffffu, v4, off));
            v5 = fmaxf(v5, __shfl_xor_sync(0xffffffffu, v5, off));
        }
        if (lane == 0) {
            sblk[0] = v0; sblk[1] = v1; sblk[2] = v2;
            sblk[3] = v3; sblk[4] = v4; sblk[5] = v5;
        }
    }

    // ---- Cluster exchange of min/max ----
    cluster.sync();
    if (tid < 3) {
        const float* peer = cluster.map_shared_rank(sblk, rank ^ 1);
        sfin[tid]     = fminf(sblk[tid],     peer[tid]);
        sfin[tid + 3] = fmaxf(sblk[tid + 3], peer[tid + 3]);
    }
    __syncthreads();
    const float fm0 = sfin[0], fm1 = sfin[1], fm2 = sfin[2];
    // Shrunken scale + interior bias: u = v*s + (t+0.5) is in
    // (0, 4) with >= 1e-6 margin at both ends; NO clamps needed.
    // Magic-number floor: z = fmaf(v, s, t) + 2^23 encodes
    // round(u - 0.5) = floor(u) in the mantissa low bits (FADD, not F2I).
    const float MAGIC = 8388608.0f;  // 2^23
    const float s0 = 3.99999f / (sfin[3] - fm0);
    const float s1 = 3.99999f / (sfin[4] - fm1);
    const float s2 = 3.99999f / (sfin[5] - fm2);
    const float t0 = (1e-6f - 0.5f) - fm0 * s0;
    const float t1 = (1e-6f - 0.5f) - fm1 * s1;
    const float t2 = (1e-6f - 0.5f) - fm2 * s2;

    // ============== Pass 2: histogram, coalesced + magic binning ==========
    int* myh = &sh[warp << 6];

    #define BIN3(px, py, pz)                                                 \
        do {                                                                 \
            float z0_ = fmaf((px), s0, t0) + MAGIC;                          \
            float z1_ = fmaf((py), s1, t1) + MAGIC;                          \
            float z2_ = fmaf((pz), s2, t2) + MAGIC;                          \
            unsigned u0_ = __float_as_uint(z0_) & 3u;                        \
            unsigned u1_ = __float_as_uint(z1_) & 3u;                        \
            unsigned u2_ = __float_as_uint(z2_) & 3u;                        \
            atomicAdd(&myh[(u0_ << 4) | (u1_ << 2) | u2_], 1);               \
        } while (0)

    // Row m has start-offset sigma=m; per-lane o_m = (m - lr) mod 3.
    const int  o0 = (3 - lr) % 3, o1 = (4 - lr) % 3, o2 = (5 - lr) % 3;
    const bool e00 = (o0 == 0), e01 = (o0 == 1);
    const bool e10 = (o1 == 0), e11 = (o1 == 1);
    const bool e20 = (o2 == 0), e21 = (o2 == 1);
    const bool r0 = (lr == 0), r1 = (lr == 1);

    for (int t = gwarp; t < nTiles; t += 2 * NWARP) {
        int b96 = t * 96;
        float4 v0 = p4[b96 + lane];
        float4 v1 = p4[b96 + 32 + lane];
        float4 v2 = p4[b96 + 64 + lane];

        float nx0 = __shfl_down_sync(0xffffffffu, v0.x, 1);
        float ny0 = __shfl_down_sync(0xffffffffu, v0.y, 1);
        float nx1 = __shfl_down_sync(0xffffffffu, v1.x, 1);
        float ny1 = __shfl_down_sync(0xffffffffu, v1.y, 1);
        float nx2 = __shfl_down_sync(0xffffffffu, v2.x, 1);
        float ny2 = __shfl_down_sync(0xffffffffu, v2.y, 1);
        float b1x = __shfl_sync(0xffffffffu, v1.x, 0);
        float b1y = __shfl_sync(0xffffffffu, v1.y, 0);
        float b2x = __shfl_sync(0xffffffffu, v2.x, 0);
        float b2y = __shfl_sync(0xffffffffu, v2.y, 0);
        if (lane == 31) { nx0 = b1x; ny0 = b1y; nx1 = b2x; ny1 = b2y; }

        // Row A-points: window f0..f4 = (v.x,v.y,v.z,v.w,nx)
        {
            float ax = e00 ? v0.x : e01 ? v0.y : v0.z;
            float ay = e00 ? v0.y : e01 ? v0.z : v0.w;
            float az = e00 ? v0.z : e01 ? v0.w : nx0;
            BIN3(ax, ay, az);
        }
        {
            float ax = e10 ? v1.x : e11 ? v1.y : v1.z;
            float ay = e10 ? v1.y : e11 ? v1.z : v1.w;
            float az = e10 ? v1.z : e11 ? v1.w : nx1;
            BIN3(ax, ay, az);
        }
        {
            float ax = e20 ? v2.x : e21 ? v2.y : v2.z;
            float ay = e20 ? v2.y : e21 ? v2.z : v2.w;
            float az = e20 ? v2.z : e21 ? v2.w : nx2;
            BIN3(ax, ay, az);
        }
        // B-point: the one row with o==0 (row index == lr): (f3,f4,f5)
        {
            float bx = r0 ? v0.w : r1 ? v1.w : v2.w;
            float by = r0 ? nx0  : r1 ? nx1  : nx2;
            float bz = r0 ? ny0  : r1 ? ny1  : ny2;
            BIN3(bx, by, bz);
        }
    }
    // Tail points
    for (int j = tailStart + ctid; j < N; j += 2 * THREADS) {
        BIN3(xb[3 * j + 0], xb[3 * j + 1], xb[3 * j + 2]);
    }
    __syncthreads();

    if (tid < BINS) {
        int s = 0;
        #pragma unroll
        for (int w = 0; w < NWARP; w++) s += sh[(w << 6) + tid];
        hfin[tid] = s;
    }

    // ---- Cluster hist merge + epilogue (rank 0) ----
    cluster.sync();
    if (rank == 0 && tid < BINS) {
        const int* peer = cluster.map_shared_rank(hfin, 1);
        sc[tid] = (float)(hfin[tid] + peer[tid]) * invN;
    }
    cluster.sync();   // rank 1 must not exit before rank 0 read its smem

    if (rank == 0) {
        __syncthreads();
        if (tid < CLS) {
            float acc = bias[tid];
            #pragma unroll
            for (int k = 0; k < BINS; k++)
                acc = fmaf(sc[k], sWt[k * CLS + tid], acc);
            out[bat * CLS + tid] = acc;
        }
    }
}

extern "C" void kernel_launch(void* const* d_in, const int* in_sizes, int n_in,
                              void* d_out, int out_size) {
    const float* x = (const float*)d_in[0];
    const float* W = (const float*)d_in[1];
    const float* b = (const float*)d_in[2];
    float* out = (float*)d_out;

    int N = in_sizes[0] / (BATCH * 3);   // 100000
    int nf4    = ((3 * N) % 4 == 0) ? (3 * N) / 4 : 0;
    int nTiles = nf4 / 96;
    int tailStart = nTiles * 128;

    dim3 grid(2, BATCH);
    k_fused<<<grid, THREADS>>>(x, W, b, out, N, nTiles, tailStart,
                               1.0f / (float)N);
}